// round 9
// baseline (speedup 1.0000x reference)
#include <cuda_runtime.h>

typedef unsigned long long u64;

__device__ __forceinline__ u64 pk2(float a, float b) {
    u64 r; asm("mov.b64 %0,{%1,%2};" : "=l"(r) : "f"(a), "f"(b)); return r;
}
__device__ __forceinline__ float2 upk(u64 v) {
    float2 r; asm("mov.b64 {%0,%1},%2;" : "=f"(r.x), "=f"(r.y) : "l"(v)); return r;
}
__device__ __forceinline__ u64 fma2(u64 a, u64 b, u64 c) {
    u64 d; asm("fma.rn.f32x2 %0,%1,%2,%3;" : "=l"(d) : "l"(a), "l"(b), "l"(c)); return d;
}
__device__ __forceinline__ u64 mul2(u64 a, u64 b) {
    u64 d; asm("mul.rn.f32x2 %0,%1,%2;" : "=l"(d) : "l"(a), "l"(b)); return d;
}

// Bloch-vector formulation (exact rewrite, verified R6):
//   z_q = s1*(rx*c2 + ry*s2) + rz*c1 ;  h_q = s1*(sx*c2 + sy*s2) + sz*c1
//   Z0 = a0 z_a + h_a z_b          Z1 = a1 z_b + h_b z_a z_c
//   Z2 = a2 z_c + h_c z_b z_d      Z3 = a3 z_d + h_d z_c
// Qubit pairs (0,1) and (2,3) evaluated in packed f32x2.
__global__ __launch_bounds__(256)
void qcnn_kernel(const float* __restrict__ x, const float* __restrict__ w,
                 float* __restrict__ out) {
    // scf[p*7 + comp][l]: pair p, qubit q=2p+l; comp 0..6 = rx,ry,rz,ra,sx,sy,sz
    __shared__ alignas(8) float scf[14][2];

    int tid = threadIdx.x;
    int t = blockIdx.x * 256 + tid;

    // w first (feeds the per-block precompute chain), then this thread's line
    float wv[6];
    if (tid < 4) {
#pragma unroll
        for (int k = 0; k < 3; k++) {
            wv[k]     = __ldg(w + tid * 3 + k);
            wv[3 + k] = __ldg(w + 12 + tid * 3 + k);
        }
    }
    const float4* xb = (const float4*)(x + (size_t)t * 12);
    float4 F0 = __ldg(xb + 0), F1 = __ldg(xb + 1), F2 = __ldg(xb + 2);

    if (tid < 4) {
        int q = tid, p = q >> 1, l = q & 1;
        // ---- layer-1 gate U1 = RZ(g)RY(b)RX(a): u00,u10 -> Bloch rotation ----
        float sa, ca, sb, cb, sg, cg;
        __sincosf(0.5f * wv[0], &sa, &ca);
        __sincosf(0.5f * wv[1], &sb, &cb);
        __sincosf(0.5f * wv[2], &sg, &cg);
        float m00r = cb * ca, m00i = sb * sa;
        float m10r = sb * ca, m10i = -cb * sa;
        float u00r = cg * m00r + sg * m00i, u00i = cg * m00i - sg * m00r;
        float u10r = cg * m10r - sg * m10i, u10i = cg * m10i + sg * m10r;
        float qt = u00r, qz = -u00i, qy = u10r, qx = -u10i;
        float r1x = 1.f - 2.f * (qy * qy + qz * qz);
        float r1y = 2.f * (qx * qy - qt * qz);
        float r1z = 2.f * (qx * qz + qt * qy);
        float r2x = 2.f * (qx * qy + qt * qz);
        float r2y = 1.f - 2.f * (qx * qx + qz * qz);
        float r2z = 2.f * (qy * qz - qt * qx);
        float r3x = 2.f * (qx * qz - qt * qy);
        float r3y = 2.f * (qy * qz + qt * qx);
        float r3z = 1.f - 2.f * (qx * qx + qy * qy);

        // ---- layer-2 gate U2 -> observable M = U2^dag Z U2 ----
        __sincosf(0.5f * wv[3], &sa, &ca);
        __sincosf(0.5f * wv[4], &sb, &cb);
        __sincosf(0.5f * wv[5], &sg, &cg);
        float n00r = cb * ca, n00i = sb * sa;
        float n01r = -sb * ca, n01i = -cb * sa;
        float n10r = sb * ca, n10i = -cb * sa;
        float n11r = cb * ca, n11i = -sb * sa;
        float v00r = cg * n00r + sg * n00i, v00i = cg * n00i - sg * n00r;
        float v01r = cg * n01r + sg * n01i, v01i = cg * n01i - sg * n01r;
        float v10r = cg * n10r - sg * n10i, v10i = cg * n10i + sg * n10r;
        float v11r = cg * n11r - sg * n11i, v11i = cg * n11i + sg * n11r;
        float ma = v00r * v00r + v00i * v00i - v10r * v10r - v10i * v10i;
        float mb = v00r * v01r + v00i * v01i - (v10r * v11r + v10i * v11i);
        float mc = v00r * v01i - v00i * v01r - (v10r * v11i - v10i * v11r);

        scf[p * 7 + 0][l] = r3x;
        scf[p * 7 + 1][l] = r3y;
        scf[p * 7 + 2][l] = r3z;
        scf[p * 7 + 3][l] = ma;
        scf[p * 7 + 4][l] = mb * r1x - mc * r2x;
        scf[p * 7 + 5][l] = mb * r1y - mc * r2y;
        scf[p * 7 + 6][l] = mb * r1z - mc * r2z;
    }
    __syncthreads();

    const float PI = 3.14159265358979323846f;
    const u64* K = (const u64*)scf;   // K[p*7 + comp]

    // MUFU trig for all 4 qubits
    float s1a, c1a, s2a, c2a, s1b, c1b, s2b, c2b;
    float s1c, c1c, s2c, c2c, s1d, c1d, s2d, c2d;
    __sincosf(PI * F0.y, &s1a, &c1a);  __sincosf(PI * F0.z, &s2a, &c2a);
    __sincosf(PI * F1.x, &s1b, &c1b);  __sincosf(PI * F1.y, &s2b, &c2b);
    __sincosf(PI * F1.w, &s1c, &c1c);  __sincosf(PI * F2.x, &s2c, &c2c);
    __sincosf(PI * F2.z, &s1d, &c1d);  __sincosf(PI * F2.w, &s2d, &c2d);

    // ---- pair (0,1) packed ----
    u64 S1 = pk2(s1a, s1b), C1 = pk2(c1a, c1b);
    u64 S2 = pk2(s2a, s2b), C2 = pk2(c2a, c2b);
    u64 tz = fma2(K[1], S2, mul2(K[0], C2));
    u64 z01 = fma2(S1, tz, mul2(K[2], C1));
    u64 th = fma2(K[5], S2, mul2(K[4], C2));
    u64 h01 = fma2(S1, th, mul2(K[6], C1));
    u64 az01 = mul2(K[3], z01);

    // ---- pair (2,3) packed ----
    S1 = pk2(s1c, s1d); C1 = pk2(c1c, c1d);
    S2 = pk2(s2c, s2d); C2 = pk2(c2c, c2d);
    tz = fma2(K[8], S2, mul2(K[7], C2));
    u64 z23 = fma2(S1, tz, mul2(K[9], C1));
    th = fma2(K[12], S2, mul2(K[11], C2));
    u64 h23 = fma2(S1, th, mul2(K[13], C1));
    u64 az23 = mul2(K[10], z23);

    float2 z01f = upk(z01), z23f = upk(z23);
    float2 h01f = upk(h01), h23f = upk(h23);
    float2 a01f = upk(az01), a23f = upk(az23);

    float4 Z;
    Z.x = fmaf(h01f.x, z01f.y, a01f.x);                 // a0 za + ha zb
    Z.y = fmaf(h01f.y, z01f.x * z23f.x, a01f.y);        // a1 zb + hb za zc
    Z.z = fmaf(h23f.x, z01f.y * z23f.y, a23f.x);        // a2 zc + hc zb zd
    Z.w = fmaf(h23f.y, z23f.x, a23f.y);                 // a3 zd + hd zc

    ((float4*)out)[t] = Z;
}

extern "C" void kernel_launch(void* const* d_in, const int* in_sizes, int n_in,
                              void* d_out, int out_size) {
    const float* x = (const float*)d_in[0];   // [128, 2048, 4, 3] f32
    const float* w = (const float*)d_in[1];   // [2, 4, 3] f32
    float* out = (float*)d_out;               // [128, 2048, 4] f32

    int nlines = in_sizes[0] / 12;            // 262144
    int block = 256;
    int grid = nlines / block;                // 1024
    qcnn_kernel<<<grid, block>>>(x, w, out);
}